// round 12
// baseline (speedup 1.0000x reference)
#include <cuda_runtime.h>
#include <cuda_bf16.h>
#include <math.h>
#include <stdint.h>

#define BB 64
#define NN 4096
#define DD 128
#define SS 8
#define HH 256
#define N_ITERS 3
#define LN_EPS 1e-5f
#define QK_SCALE 0.08838834764831845f
#define CHUNK 64
#define NCHUNK (NN / CHUNK)

// ---------------- device scratch ----------------
__device__ float g_K[BB * NN * DD];
__device__ float g_V[BB * NN * DD];
__device__ float g_slots[BB * SS * DD];
__device__ float g_q[BB * SS * DD];
__device__ float g_updp[NCHUNK * BB * SS * DD];
__device__ float g_normp[NCHUNK * BB * SS];
__device__ float g_wqt[DD * DD];
__device__ float g_wiht[DD * 3 * DD];
__device__ float g_whht[DD * 3 * DD];
__device__ float g_w1t[DD * HH];
__device__ float g_w2t[HH * DD];

__device__ __forceinline__ uint32_t smem_u32(const void* p) {
    uint32_t a;
    asm("{ .reg .u64 t; cvta.to.shared.u64 t, %1; cvt.u32.u64 %0, t; }"
        : "=r"(a) : "l"(p));
    return a;
}
__device__ __forceinline__ void ldsm_x4(uint32_t* r, uint32_t addr) {
    asm volatile("ldmatrix.sync.aligned.m8n8.x4.shared.b16 {%0,%1,%2,%3}, [%4];"
                 : "=r"(r[0]), "=r"(r[1]), "=r"(r[2]), "=r"(r[3]) : "r"(addr));
}
__device__ __forceinline__ void mma_bf16(float* c, const uint32_t* a, const uint32_t* b) {
    asm volatile(
        "mma.sync.aligned.m16n8k16.row.col.f32.bf16.bf16.f32 "
        "{%0,%1,%2,%3}, {%4,%5,%6,%7}, {%8,%9}, {%0,%1,%2,%3};"
        : "+f"(c[0]), "+f"(c[1]), "+f"(c[2]), "+f"(c[3])
        : "r"(a[0]), "r"(a[1]), "r"(a[2]), "r"(a[3]), "r"(b[0]), "r"(b[1]));
}

// smem layout for sa_kv (bytes); pitch 136 bf16 (272B) de-conflicts ldmatrix
#define PA 136
#define S_BIAS 0
#define S_BH 1024
#define S_BL (S_BH + 256 * PA * 2)
#define S_AH (S_BL + 256 * PA * 2)
#define S_AL (S_AH + 128 * PA * 2)
#define KV_SMEM_TOTAL (S_AL + 128 * PA * 2)

// ---------------- weight transposes + slot init ----------------
__global__ void sa_prep(const float* __restrict__ wq, const float* __restrict__ wih,
                        const float* __restrict__ whh, const float* __restrict__ w1,
                        const float* __restrict__ w2, const float* __restrict__ mu,
                        const float* __restrict__ ls, const float* __restrict__ noise) {
    int i = blockIdx.x * blockDim.x + threadIdx.x;
    if (i < DD * DD)  { int a = i / DD, j = i % DD; g_wqt[i] = wq[j * DD + a]; }
    if (i < DD * 384) { int d = i / 384, g = i % 384;
        g_wiht[i] = wih[g * DD + d]; g_whht[i] = whh[g * DD + d]; }
    if (i < DD * HH)  { int j = i / HH, m = i % HH; g_w1t[i] = w1[m * DD + j]; }
    if (i < HH * DD)  { int m = i / DD, j = i % DD; g_w2t[i] = w2[j * HH + m]; }
    if (i < SS * DD) {
        float v = mu[i] + expf(ls[i]) * noise[i];
        for (int b = 0; b < BB; ++b) g_slots[b * SS * DD + i] = v;
    }
}

// -------- LN(inputs) + K/V projection via mma.sync bf16-split, 16 warps -------
// Warp w: rows ((w&7)*16 .. +15), col-half ch = w>>3 (nt = ch*16 .. ch*16+15).
// B fragments via ldmatrix.x4 over nt pairs.
__global__ __launch_bounds__(512, 1)
void sa_kv(const float* __restrict__ inp, const float* __restrict__ nig,
           const float* __restrict__ nib, const float* __restrict__ bk,
           const float* __restrict__ bv, const float* __restrict__ wk,
           const float* __restrict__ wv) {
    extern __shared__ __align__(128) char smem[];
    const uint32_t sb = smem_u32(smem);
    const int tid = threadIdx.x;
    const int wid = tid >> 5;
    const int lane = tid & 31;

    // split weights into smem (persistent): rows 0..127 wk, 128..255 wv
    for (int idx = tid; idx < 256 * DD; idx += 512) {
        int row = idx >> 7, k = idx & 127;
        float w = (row < 128) ? wk[row * DD + k] : wv[(row - 128) * DD + k];
        __nv_bfloat16 hi = __float2bfloat16(w);
        __nv_bfloat16 lo = __float2bfloat16(w - __bfloat162float(hi));
        uint32_t off = (uint32_t)(row * PA + k) * 2;
        *(__nv_bfloat16*)(smem + S_BH + off) = hi;
        *(__nv_bfloat16*)(smem + S_BL + off) = lo;
    }
    for (int c = tid; c < 256; c += 512)
        *(float*)(smem + S_BIAS + c * 4) = (c < DD) ? bk[c] : bv[c - DD];

    float4 lg4 = *(const float4*)(nig + lane * 4);
    float4 lb4 = *(const float4*)(nib + lane * 4);

    // A ldmatrix lane addressing
    const int a_rr = lane & 7;
    const int a_g  = lane >> 3;
    const int a_ro = a_rr + ((a_g & 1) ? 8 : 0);
    const int a_ko = (a_g & 2) ? 8 : 0;
    // B x4 lane addressing: matrices {nt,k0},{nt,k0+8},{nt+1,k0},{nt+1,k0+8}
    const int b_mrow = lane & 7;
    const int b_sel  = lane >> 3;
    const int b_ntl  = b_sel >> 1;        // 0 or 1 (which nt of the pair)
    const int b_kadd = (b_sel & 1) * 8;
    const int r0 = (wid & 7) * 16;
    const int ch = wid >> 3;
    const int base_nt = ch * 16;

    const int ntiles = BB * NN / 128;   // 2048
    for (int tile = blockIdx.x; tile < ntiles; tile += gridDim.x) {
        size_t m0 = (size_t)tile * 128;
        // LN + bf16 split: warp handles rows wid*8 .. +7
        #pragma unroll
        for (int rr = 0; rr < 8; ++rr) {
            int row = wid * 8 + rr;
            float4 xv = *(const float4*)(inp + (m0 + row) * DD + lane * 4);
            float s1 = xv.x + xv.y + xv.z + xv.w;
            float s2 = xv.x * xv.x + xv.y * xv.y + xv.z * xv.z + xv.w * xv.w;
            #pragma unroll
            for (int o = 16; o > 0; o >>= 1) {
                s1 += __shfl_xor_sync(0xffffffffu, s1, o);
                s2 += __shfl_xor_sync(0xffffffffu, s2, o);
            }
            float muv = s1 * (1.f / DD);
            float var = s2 * (1.f / DD) - muv * muv;
            float rs = rsqrtf(var + LN_EPS);
            float x0 = (xv.x - muv) * rs * lg4.x + lb4.x;
            float x1 = (xv.y - muv) * rs * lg4.y + lb4.y;
            float x2 = (xv.z - muv) * rs * lg4.z + lb4.z;
            float x3 = (xv.w - muv) * rs * lg4.w + lb4.w;
            __nv_bfloat16 h0 = __float2bfloat16(x0), h1 = __float2bfloat16(x1);
            __nv_bfloat16 h2 = __float2bfloat16(x2), h3 = __float2bfloat16(x3);
            __nv_bfloat16 l0 = __float2bfloat16(x0 - __bfloat162float(h0));
            __nv_bfloat16 l1 = __float2bfloat16(x1 - __bfloat162float(h1));
            __nv_bfloat16 l2 = __float2bfloat16(x2 - __bfloat162float(h2));
            __nv_bfloat16 l3 = __float2bfloat16(x3 - __bfloat162float(h3));
            uint2 hv, lv;
            hv.x = ((uint32_t)__bfloat16_as_ushort(h1) << 16) | __bfloat16_as_ushort(h0);
            hv.y = ((uint32_t)__bfloat16_as_ushort(h3) << 16) | __bfloat16_as_ushort(h2);
            lv.x = ((uint32_t)__bfloat16_as_ushort(l1) << 16) | __bfloat16_as_ushort(l0);
            lv.y = ((uint32_t)__bfloat16_as_ushort(l3) << 16) | __bfloat16_as_ushort(l2);
            uint32_t off = (uint32_t)(row * PA + lane * 4) * 2;
            *(uint2*)(smem + S_AH + off) = hv;
            *(uint2*)(smem + S_AL + off) = lv;
        }
        __syncthreads();
        // warp MMA: 16 rows x 128 cols (16 nt), K=128, 3 bf16-split passes
        float acc[16][4];
        #pragma unroll
        for (int nt = 0; nt < 16; ++nt) {
            acc[nt][0] = 0.f; acc[nt][1] = 0.f; acc[nt][2] = 0.f; acc[nt][3] = 0.f;
        }
        #pragma unroll 1
        for (int ks = 0; ks < 8; ++ks) {
            int k0 = ks * 16;
            uint32_t ah[4], al[4];
            uint32_t aoff = (uint32_t)((r0 + a_ro) * PA + k0 + a_ko) * 2;
            ldsm_x4(ah, sb + S_AH + aoff);
            ldsm_x4(al, sb + S_AL + aoff);
            #pragma unroll
            for (int p = 0; p < 8; ++p) {
                int ntg = base_nt + 2 * p;              // global nt of pair
                uint32_t brow = (uint32_t)((ntg + b_ntl) * 8 + b_mrow);
                uint32_t boff = (brow * PA + k0 + b_kadd) * 2;
                uint32_t bh[4], bl[4];
                ldsm_x4(bh, sb + S_BH + boff);
                ldsm_x4(bl, sb + S_BL + boff);
                mma_bf16(acc[2 * p],     ah, bh);
                mma_bf16(acc[2 * p],     ah, bl);
                mma_bf16(acc[2 * p],     al, bh);
                mma_bf16(acc[2 * p + 1], ah, bh + 2);
                mma_bf16(acc[2 * p + 1], ah, bl + 2);
                mma_bf16(acc[2 * p + 1], al, bh + 2);
            }
        }
        __syncthreads();   // A smem free for next tile's LN
        // epilogue: direct float2 stores (rows r, r+8)
        {
            int rbase = (int)(m0 + r0 + (lane >> 2));
            int cq = (lane & 3) * 2;
            #pragma unroll
            for (int j = 0; j < 16; ++j) {
                int nt = base_nt + j;
                int col = nt * 8 + cq;
                float2 bias = *(float2*)(smem + S_BIAS + col * 4);
                float* base = (nt < 16) ? g_K : g_V;
                int c = (nt < 16) ? col : col - 128;
                *(float2*)(base + (size_t)rbase * DD + c)
                    = make_float2(acc[j][0] + bias.x, acc[j][1] + bias.y);
                *(float2*)(base + (size_t)(rbase + 8) * DD + c)
                    = make_float2(acc[j][2] + bias.x, acc[j][3] + bias.y);
            }
        }
    }
}

// ---------------- q = LN(slots; ns) @ wq^T + bq ----------------
__global__ __launch_bounds__(128)
void sa_q(const float* __restrict__ nsg, const float* __restrict__ nsb,
          const float* __restrict__ bq) {
    __shared__ float xn[DD];
    __shared__ float rs1[4], rs2[4];
    int row = blockIdx.x;
    int tid = threadIdx.x;
    int lane = tid & 31, w = tid >> 5;
    float x = g_slots[row * DD + tid];
    float s1 = x, s2 = x * x;
    #pragma unroll
    for (int o = 16; o > 0; o >>= 1) {
        s1 += __shfl_xor_sync(0xffffffffu, s1, o);
        s2 += __shfl_xor_sync(0xffffffffu, s2, o);
    }
    if (lane == 0) { rs1[w] = s1; rs2[w] = s2; }
    __syncthreads();
    float sum = rs1[0] + rs1[1] + rs1[2] + rs1[3];
    float sq  = rs2[0] + rs2[1] + rs2[2] + rs2[3];
    float mu = sum * (1.f / DD);
    float var = sq * (1.f / DD) - mu * mu;
    float rstd = rsqrtf(var + LN_EPS);
    xn[tid] = (x - mu) * rstd * nsg[tid] + nsb[tid];
    __syncthreads();
    float acc = bq[tid];
    #pragma unroll 4
    for (int i = 0; i < DD; ++i) acc += xn[i] * g_wqt[i * DD + tid];
    g_q[row * DD + tid] = acc;
}

// ---------------- fused attention over one 64-token chunk ----------------
#define ATTN_SMEM ((128 * 65 + SS * DD + CHUNK * SS + 2 * SS * DD) * 4)
__global__ __launch_bounds__(256, 4)
void sa_attn() {
    extern __shared__ float sm[];
    float* Kst  = sm;
    float* qs   = Kst + 128 * 65;
    float* att  = qs + SS * DD;
    float* updp = att + CHUNK * SS;
    const int tid = threadIdx.x;
    const int b = blockIdx.y;
    const int n0 = blockIdx.x * CHUNK;
    {
        const float4* s4 = (const float4*)(g_q + b * SS * DD);
        float4* d4 = (float4*)qs;
        for (int i = tid; i < SS * DD / 4; i += 256) d4[i] = s4[i];
    }
    const float* Kp = g_K + ((size_t)b * NN + n0) * DD;
    for (int i4 = tid; i4 < CHUNK * 32; i4 += 256) {
        float4 kv = ((const float4*)Kp)[i4];
        int tok = i4 >> 5;
        int c = (i4 & 31) * 4;
        Kst[(c + 0) * 65 + tok] = kv.x;
        Kst[(c + 1) * 65 + tok] = kv.y;
        Kst[(c + 2) * 65 + tok] = kv.z;
        Kst[(c + 3) * 65 + tok] = kv.w;
    }
    __syncthreads();
    {
        const int t = tid & 63;
        const int s0 = (tid >> 6) * 2;
        float l0 = 0.f, l1 = 0.f;
        const float* q0p = qs + s0 * DD;
        const float* q1p = qs + (s0 + 1) * DD;
        #pragma unroll 4
        for (int k = 0; k < DD; k += 4) {
            float k0 = Kst[(k + 0) * 65 + t];
            float k1 = Kst[(k + 1) * 65 + t];
            float k2 = Kst[(k + 2) * 65 + t];
            float k3 = Kst[(k + 3) * 65 + t];
            float4 a0 = *(const float4*)(q0p + k);
            float4 a1 = *(const float4*)(q1p + k);
            l0 += k0 * a0.x + k1 * a0.y + k2 * a0.z + k3 * a0.w;
            l1 += k0 * a1.x + k1 * a1.y + k2 * a1.z + k3 * a1.w;
        }
        att[t * 8 + s0]     = l0 * QK_SCALE;
        att[t * 8 + s0 + 1] = l1 * QK_SCALE;
    }
    __syncthreads();
    if (tid < CHUNK) {
        float l[8];
        #pragma unroll
        for (int s = 0; s < 8; ++s) l[s] = att[tid * 8 + s];
        float mx = l[0];
        #pragma unroll
        for (int s = 1; s < 8; ++s) mx = fmaxf(mx, l[s]);
        float sum = 0.f;
        #pragma unroll
        for (int s = 0; s < 8; ++s) { l[s] = expf(l[s] - mx); sum += l[s]; }
        float inv = 1.f / sum;
        #pragma unroll
        for (int s = 0; s < 8; ++s) att[tid * 8 + s] = l[s] * inv;
    }
    __syncthreads();
    {
        int w = tid >> 5, lane = tid & 31;
        float v = att[lane * 8 + w] + att[(lane + 32) * 8 + w];
        #pragma unroll
        for (int o = 16; o > 0; o >>= 1) v += __shfl_xor_sync(0xffffffffu, v, o);
        if (lane == 0) g_normp[((size_t)blockIdx.x * BB + b) * SS + w] = v;
    }
    const float* Vp = g_V + ((size_t)b * NN + n0) * DD;
    {
        const int g = tid >> 7;
        const int u = tid & 127;
        const int dp = (u & 63) * 2;
        const int shalf = u >> 6;
        float ax[4], ay[4];
        #pragma unroll
        for (int s = 0; s < 4; ++s) { ax[s] = 0.f; ay[s] = 0.f; }
        #pragma unroll 2
        for (int tt = 0; tt < 32; ++tt) {
            int t = g * 32 + tt;
            float2 vv = *(const float2*)(Vp + t * DD + dp);
            float4 w4 = *(const float4*)(att + t * 8 + shalf * 4);
            ax[0] += w4.x * vv.x; ay[0] += w4.x * vv.y;
            ax[1] += w4.y * vv.x; ay[1] += w4.y * vv.y;
            ax[2] += w4.z * vv.x; ay[2] += w4.z * vv.y;
            ax[3] += w4.w * vv.x; ay[3] += w4.w * vv.y;
        }
        #pragma unroll
        for (int s = 0; s < 4; ++s)
            *(float2*)(updp + (g * SS + shalf * 4 + s) * DD + dp)
                = make_float2(ax[s], ay[s]);
    }
    __syncthreads();
    float* dst = g_updp + ((size_t)blockIdx.x * BB + b) * (SS * DD);
    for (int o = tid; o < SS * DD; o += 256)
        dst[o] = updp[o] + updp[o + SS * DD];
}

// ------- GRU + MLP slot update with fused chunk-reduce: block per (b, s-pair) --
__global__ __launch_bounds__(128)
void sa_update(const float* __restrict__ bih, const float* __restrict__ bhh,
               const float* __restrict__ mg, const float* __restrict__ mb,
               const float* __restrict__ b1, const float* __restrict__ b2,
               float* __restrict__ outbuf, int write_out) {
    __shared__ float su0[DD], su1[DD], sh0[DD], sh1[DD];
    __shared__ float sn0[DD], sn1[DD], xn0[DD], xn1[DD];
    __shared__ float h10[HH], h11[HH];
    __shared__ float red[16];
    __shared__ float nrm[2];
    const int b = blockIdx.x >> 2;
    const int s0 = (blockIdx.x & 3) * 2;
    const int j = threadIdx.x;
    const int lane = j & 31, w = j >> 5;
    // fused norm reduce: threads 0..63 -> slot s0, 64..127 -> slot s0+1
    {
        int sl = j >> 6, c = j & 63;
        float ns = g_normp[((size_t)c * BB + b) * SS + s0 + sl];
        #pragma unroll
        for (int o = 16; o > 0; o >>= 1) ns += __shfl_xor_sync(0xffffffffu, ns, o);
        if (lane == 0) red[w] = ns;
    }
    // fused update reduce over 64 chunks (coalesced 128-wide rows)
    {
        float a0 = 0.f, a1 = 0.f;
        const size_t o0 = (size_t)s0 * DD + j;
        #pragma unroll 4
        for (int c = 0; c < NCHUNK; ++c) {
            const float* src = g_updp + ((size_t)c * BB + b) * (SS * DD);
            a0 += src[o0];
            a1 += src[o0 + DD];
        }
        __syncthreads();
        float n0 = fmaxf(red[0] + red[1], 1e-8f);
        float n1 = fmaxf(red[2] + red[3], 1e-8f);
        su0[j] = a0 / n0;
        su1[j] = a1 / n1;
        sh0[j] = g_slots[(b * SS + s0) * DD + j];
        sh1[j] = g_slots[(b * SS + s0 + 1) * DD + j];
    }
    __syncthreads();
    float ir0 = 0, iz0 = 0, in0 = 0, hr0 = 0, hz0 = 0, hn0 = 0;
    float ir1 = 0, iz1 = 0, in1 = 0, hr1 = 0, hz1 = 0, hn1 = 0;
    #pragma unroll 4
    for (int d = 0; d < DD; ++d) {
        float wr = g_wiht[d * 384 + j];
        float wz = g_wiht[d * 384 + 128 + j];
        float wn = g_wiht[d * 384 + 256 + j];
        float vr = g_whht[d * 384 + j];
        float vz = g_whht[d * 384 + 128 + j];
        float vn = g_whht[d * 384 + 256 + j];
        float u0 = su0[d], u1 = su1[d], h0 = sh0[d], h1 = sh1[d];
        ir0 += wr * u0; iz0 += wz * u0; in0 += wn * u0;
        hr0 += vr * h0; hz0 += vz * h0; hn0 += vn * h0;
        ir1 += wr * u1; iz1 += wz * u1; in1 += wn * u1;
        hr1 += vr * h1; hz1 += vz * h1; hn1 += vn * h1;
    }
    {
        float bir = bih[j], biz = bih[j + 128], bin = bih[j + 256];
        float bhr = bhh[j], bhz = bhh[j + 128], bhn = bhh[j + 256];
        float r0 = 1.f / (1.f + expf(-(ir0 + bir + hr0 + bhr)));
        float z0 = 1.f / (1.f + expf(-(iz0 + biz + hz0 + bhz)));
        float n0 = tanhf(in0 + bin + r0 * (hn0 + bhn));
        sn0[j] = (1.f - z0) * n0 + z0 * sh0[j];
        float r1 = 1.f / (1.f + expf(-(ir1 + bir + hr1 + bhr)));
        float z1 = 1.f / (1.f + expf(-(iz1 + biz + hz1 + bhz)));
        float n1 = tanhf(in1 + bin + r1 * (hn1 + bhn));
        sn1[j] = (1.f - z1) * n1 + z1 * sh1[j];
    }
    __syncthreads();
    {
        float a = sn0[j], c = sn1[j];
        float s1a = a, s2a = a * a, s1c = c, s2c = c * c;
        #pragma unroll
        for (int o = 16; o > 0; o >>= 1) {
            s1a += __shfl_xor_sync(0xffffffffu, s1a, o);
            s2a += __shfl_xor_sync(0xffffffffu, s2a, o);
            s1c += __shfl_xor_sync(0xffffffffu, s1c, o);
            s2c += __shfl_xor_sync(0xffffffffu, s2c, o);
        }
        if (lane == 0) { red[w] = s1a; red[w + 4] = s2a; red[w + 8] = s1c; red[w + 12] = s2c; }
        __syncthreads();
        float m0 = (red[0] + red[1] + red[2] + red[3]) * (1.f / DD);
        float v0 = (red[4] + red[5] + red[6] + red[7]) * (1.f / DD) - m0 * m0;
        float m1 = (red[8] + red[9] + red[10] + red[11]) * (1.f / DD);
        float v1 = (red[12] + red[13] + red[14] + red[15]) * (1.f / DD) - m1 * m1;
        float r0 = rsqrtf(v0 + LN_EPS), r1 = rsqrtf(v1 + LN_EPS);
        float mgj = mg[j], mbj = mb[j];
        xn0[j] = (a - m0) * r0 * mgj + mbj;
        xn1[j] = (c - m1) * r1 * mgj + mbj;
    }
    __syncthreads();
    {
        float acc00 = 0, acc01 = 0, acc10 = 0, acc11 = 0;
        #pragma unroll 4
        for (int d = 0; d < DD; ++d) {
            float wa = g_w1t[d * HH + j];
            float wb = g_w1t[d * HH + j + 128];
            float x0 = xn0[d], x1 = xn1[d];
            acc00 += x0 * wa; acc01 += x0 * wb;
            acc10 += x1 * wa; acc11 += x1 * wb;
        }
        float b1a = b1[j], b1b = b1[j + 128];
        float g00 = acc00 + b1a, g01 = acc01 + b1b;
        float g10 = acc10 + b1a, g11 = acc11 + b1b;
        h10[j]       = 0.5f * g00 * (1.f + erff(g00 * 0.7071067811865475f));
        h10[j + 128] = 0.5f * g01 * (1.f + erff(g01 * 0.7071067811865475f));
        h11[j]       = 0.5f * g10 * (1.f + erff(g10 * 0.7071067811865475f));
        h11[j + 128] = 0.5f * g11 * (1.f + erff(g11 * 0.7071067811865475f));
    }
    __syncthreads();
    {
        float o0 = 0, o1 = 0;
        #pragma unroll 4
        for (int m = 0; m < HH; ++m) {
            float w2v = g_w2t[m * DD + j];
            o0 += h10[m] * w2v;
            o1 += h11[m] * w2v;
        }
        float b2j = b2[j];
        float v0 = sn0[j] + o0 + b2j;
        float v1 = sn1[j] + o1 + b2j;
        if (write_out) {
            outbuf[(b * SS + s0) * DD + j] = v0;
            outbuf[(b * SS + s0 + 1) * DD + j] = v1;
        } else {
            g_slots[(b * SS + s0) * DD + j] = v0;
            g_slots[(b * SS + s0 + 1) * DD + j] = v1;
        }
    }
}

// ---------------- launch ----------------
extern "C" void kernel_launch(void* const* d_in, const int* in_sizes, int n_in,
                              void* d_out, int out_size) {
    const float* inputs = (const float*)d_in[0];
    const float* noise  = (const float*)d_in[1];
    const float* mu     = (const float*)d_in[2];
    const float* lsig   = (const float*)d_in[3];
    const float* wq     = (const float*)d_in[4];
    const float* bq     = (const float*)d_in[5];
    const float* wk     = (const float*)d_in[6];
    const float* bk     = (const float*)d_in[7];
    const float* wv     = (const float*)d_in[8];
    const float* bv     = (const float*)d_in[9];
    const float* gwih   = (const float*)d_in[10];
    const float* gwhh   = (const float*)d_in[11];
    const float* gbih   = (const float*)d_in[12];
    const float* gbhh   = (const float*)d_in[13];
    const float* nsg    = (const float*)d_in[14];
    const float* nsb    = (const float*)d_in[15];
    const float* nig    = (const float*)d_in[16];
    const float* nib    = (const float*)d_in[17];
    const float* mlg    = (const float*)d_in[18];
    const float* mlb    = (const float*)d_in[19];
    const float* w1     = (const float*)d_in[20];
    const float* b1     = (const float*)d_in[21];
    const float* w2     = (const float*)d_in[22];
    const float* b2     = (const float*)d_in[23];
    float* out = (float*)d_out;

    cudaFuncSetAttribute(sa_kv,   cudaFuncAttributeMaxDynamicSharedMemorySize, KV_SMEM_TOTAL);
    cudaFuncSetAttribute(sa_attn, cudaFuncAttributeMaxDynamicSharedMemorySize, ATTN_SMEM);

    sa_prep<<<(DD * 384 + 255) / 256, 256>>>(wq, gwih, gwhh, w1, w2, mu, lsig, noise);
    sa_kv<<<148, 512, KV_SMEM_TOTAL>>>(inputs, nig, nib, bk, bv, wk, wv);
    for (int it = 0; it < N_ITERS; ++it) {
        sa_q<<<BB * SS, 128>>>(nsg, nsb, bq);
        dim3 agrid(NCHUNK, BB);
        sa_attn<<<agrid, 256, ATTN_SMEM>>>();
        sa_update<<<BB * 4, 128>>>(gbih, gbhh, mlg, mlb, b1, b2,
                                   out, it == N_ITERS - 1 ? 1 : 0);
    }
}

// round 13
// speedup vs baseline: 1.4517x; 1.4517x over previous
#include <cuda_runtime.h>
#include <cuda_bf16.h>
#include <math.h>
#include <stdint.h>

#define BB 64
#define NN 4096
#define DD 128
#define SS 8
#define HH 256
#define N_ITERS 3
#define LN_EPS 1e-5f
#define QK_SCALE 0.08838834764831845f
#define CHUNK 64
#define NCHUNK (NN / CHUNK)

// ---------------- device scratch ----------------
__device__ float g_K[BB * NN * DD];
__device__ float g_V[BB * NN * DD];
__device__ float g_slots[BB * SS * DD];
__device__ float g_q[BB * SS * DD];
__device__ float g_updp[NCHUNK * BB * SS * DD];
__device__ float g_normp[NCHUNK * BB * SS];
__device__ float g_wqt[DD * DD];
__device__ float g_wiht[DD * 3 * DD];
__device__ float g_whht[DD * 3 * DD];
__device__ float g_w1t[DD * HH];
__device__ float g_w2t[HH * DD];

__device__ __forceinline__ uint32_t smem_u32(const void* p) {
    uint32_t a;
    asm("{ .reg .u64 t; cvta.to.shared.u64 t, %1; cvt.u32.u64 %0, t; }"
        : "=r"(a) : "l"(p));
    return a;
}
__device__ __forceinline__ void ldsm_x4(uint32_t* r, uint32_t addr) {
    asm volatile("ldmatrix.sync.aligned.m8n8.x4.shared.b16 {%0,%1,%2,%3}, [%4];"
                 : "=r"(r[0]), "=r"(r[1]), "=r"(r[2]), "=r"(r[3]) : "r"(addr));
}
__device__ __forceinline__ void ldsm_x2(uint32_t* r, uint32_t addr) {
    asm volatile("ldmatrix.sync.aligned.m8n8.x2.shared.b16 {%0,%1}, [%2];"
                 : "=r"(r[0]), "=r"(r[1]) : "r"(addr));
}
__device__ __forceinline__ void mma_bf16(float* c, const uint32_t* a, const uint32_t* b) {
    asm volatile(
        "mma.sync.aligned.m16n8k16.row.col.f32.bf16.bf16.f32 "
        "{%0,%1,%2,%3}, {%4,%5,%6,%7}, {%8,%9}, {%0,%1,%2,%3};"
        : "+f"(c[0]), "+f"(c[1]), "+f"(c[2]), "+f"(c[3])
        : "r"(a[0]), "r"(a[1]), "r"(a[2]), "r"(a[3]), "r"(b[0]), "r"(b[1]));
}

// smem layout for sa_kv (bytes); pitch 136 bf16 (272B) de-conflicts ldmatrix
#define PA 136
#define S_BIAS 0
#define S_BH 1024
#define S_BL (S_BH + 256 * PA * 2)
#define S_AH (S_BL + 256 * PA * 2)
#define S_AL (S_AH + 128 * PA * 2)
#define KV_SMEM_TOTAL (S_AL + 128 * PA * 2)

__global__ void sa_nop() {}

// ---------------- weight transposes + slot init ----------------
__global__ void sa_prep(const float* __restrict__ wq, const float* __restrict__ wih,
                        const float* __restrict__ whh, const float* __restrict__ w1,
                        const float* __restrict__ w2, const float* __restrict__ mu,
                        const float* __restrict__ ls, const float* __restrict__ noise) {
    int i = blockIdx.x * blockDim.x + threadIdx.x;
    if (i < DD * DD)  { int a = i / DD, j = i % DD; g_wqt[i] = wq[j * DD + a]; }
    if (i < DD * 384) { int d = i / 384, g = i % 384;
        g_wiht[i] = wih[g * DD + d]; g_whht[i] = whh[g * DD + d]; }
    if (i < DD * HH)  { int j = i / HH, m = i % HH; g_w1t[i] = w1[m * DD + j]; }
    if (i < HH * DD)  { int m = i / DD, j = i % DD; g_w2t[i] = w2[j * HH + m]; }
    if (i < SS * DD) {
        float v = mu[i] + expf(ls[i]) * noise[i];
        for (int b = 0; b < BB; ++b) g_slots[b * SS * DD + i] = v;
    }
}

// -------- LN(inputs) + K/V projection via mma.sync bf16-split (3 passes) -------
// (identical to round-11 version: 256 threads, 8 warps, warp = 16 rows x 256 cols)
__global__ __launch_bounds__(256, 1)
void sa_kv(const float* __restrict__ inp, const float* __restrict__ nig,
           const float* __restrict__ nib, const float* __restrict__ bk,
           const float* __restrict__ bv, const float* __restrict__ wk,
           const float* __restrict__ wv) {
    extern __shared__ __align__(128) char smem[];
    const uint32_t sb = smem_u32(smem);
    const int tid = threadIdx.x;
    const int wid = tid >> 5;
    const int lane = tid & 31;

    for (int idx = tid; idx < 256 * DD; idx += 256) {
        int row = idx >> 7, k = idx & 127;
        float w = (row < 128) ? wk[row * DD + k] : wv[(row - 128) * DD + k];
        __nv_bfloat16 hi = __float2bfloat16(w);
        __nv_bfloat16 lo = __float2bfloat16(w - __bfloat162float(hi));
        uint32_t off = (uint32_t)(row * PA + k) * 2;
        *(__nv_bfloat16*)(smem + S_BH + off) = hi;
        *(__nv_bfloat16*)(smem + S_BL + off) = lo;
    }
    for (int c = tid; c < 256; c += 256)
        *(float*)(smem + S_BIAS + c * 4) = (c < DD) ? bk[c] : bv[c - DD];

    float4 lg4 = *(const float4*)(nig + lane * 4);
    float4 lb4 = *(const float4*)(nib + lane * 4);

    const int a_rr = lane & 7;
    const int a_g  = lane >> 3;
    const int a_ro = a_rr + ((a_g & 1) ? 8 : 0);
    const int a_ko = (a_g & 2) ? 8 : 0;
    const int b_rr = lane & 7;
    const int b_ko = (lane & 8) ? 8 : 0;
    const int r0 = wid * 16;

    const int ntiles = BB * NN / 128;   // 2048
    for (int tile = blockIdx.x; tile < ntiles; tile += gridDim.x) {
        size_t m0 = (size_t)tile * 128;
        #pragma unroll
        for (int rr = 0; rr < 16; ++rr) {
            int row = wid * 16 + rr;
            float4 xv = *(const float4*)(inp + (m0 + row) * DD + lane * 4);
            float s1 = xv.x + xv.y + xv.z + xv.w;
            float s2 = xv.x * xv.x + xv.y * xv.y + xv.z * xv.z + xv.w * xv.w;
            #pragma unroll
            for (int o = 16; o > 0; o >>= 1) {
                s1 += __shfl_xor_sync(0xffffffffu, s1, o);
                s2 += __shfl_xor_sync(0xffffffffu, s2, o);
            }
            float muv = s1 * (1.f / DD);
            float var = s2 * (1.f / DD) - muv * muv;
            float rs = rsqrtf(var + LN_EPS);
            float x0 = (xv.x - muv) * rs * lg4.x + lb4.x;
            float x1 = (xv.y - muv) * rs * lg4.y + lb4.y;
            float x2 = (xv.z - muv) * rs * lg4.z + lb4.z;
            float x3 = (xv.w - muv) * rs * lg4.w + lb4.w;
            __nv_bfloat16 h0 = __float2bfloat16(x0), h1 = __float2bfloat16(x1);
            __nv_bfloat16 h2 = __float2bfloat16(x2), h3 = __float2bfloat16(x3);
            __nv_bfloat16 l0 = __float2bfloat16(x0 - __bfloat162float(h0));
            __nv_bfloat16 l1 = __float2bfloat16(x1 - __bfloat162float(h1));
            __nv_bfloat16 l2 = __float2bfloat16(x2 - __bfloat162float(h2));
            __nv_bfloat16 l3 = __float2bfloat16(x3 - __bfloat162float(h3));
            uint2 hv, lv;
            hv.x = ((uint32_t)__bfloat16_as_ushort(h1) << 16) | __bfloat16_as_ushort(h0);
            hv.y = ((uint32_t)__bfloat16_as_ushort(h3) << 16) | __bfloat16_as_ushort(h2);
            lv.x = ((uint32_t)__bfloat16_as_ushort(l1) << 16) | __bfloat16_as_ushort(l0);
            lv.y = ((uint32_t)__bfloat16_as_ushort(l3) << 16) | __bfloat16_as_ushort(l2);
            uint32_t off = (uint32_t)(row * PA + lane * 4) * 2;
            *(uint2*)(smem + S_AH + off) = hv;
            *(uint2*)(smem + S_AL + off) = lv;
        }
        __syncthreads();
        float acc[32][4];
        #pragma unroll
        for (int nt = 0; nt < 32; ++nt) {
            acc[nt][0] = 0.f; acc[nt][1] = 0.f; acc[nt][2] = 0.f; acc[nt][3] = 0.f;
        }
        #pragma unroll 1
        for (int ks = 0; ks < 8; ++ks) {
            int k0 = ks * 16;
            uint32_t ah[4], al[4];
            uint32_t aoff = (uint32_t)((r0 + a_ro) * PA + k0 + a_ko) * 2;
            ldsm_x4(ah, sb + S_AH + aoff);
            ldsm_x4(al, sb + S_AL + aoff);
            uint32_t boff = (uint32_t)(b_rr * PA + k0 + b_ko) * 2;
            #pragma unroll
            for (int nt = 0; nt < 32; ++nt) {
                uint32_t bo = boff + (uint32_t)(nt * 8 * PA) * 2;
                uint32_t bh[2], bl[2];
                ldsm_x2(bh, sb + S_BH + bo);
                ldsm_x2(bl, sb + S_BL + bo);
                mma_bf16(acc[nt], ah, bh);
                mma_bf16(acc[nt], ah, bl);
                mma_bf16(acc[nt], al, bh);
            }
        }
        __syncthreads();
        {
            int rbase = (int)(m0 + r0 + (lane >> 2));
            int cq = (lane & 3) * 2;
            #pragma unroll
            for (int nt = 0; nt < 32; ++nt) {
                int col = nt * 8 + cq;
                float2 bias = *(float2*)(smem + S_BIAS + col * 4);
                float* base = (nt < 16) ? g_K : g_V;
                int c = (nt < 16) ? col : col - 128;
                *(float2*)(base + (size_t)rbase * DD + c)
                    = make_float2(acc[nt][0] + bias.x, acc[nt][1] + bias.y);
                *(float2*)(base + (size_t)(rbase + 8) * DD + c)
                    = make_float2(acc[nt][2] + bias.x, acc[nt][3] + bias.y);
            }
        }
    }
}

// ---------------- q = LN(slots; ns) @ wq^T + bq ----------------
__global__ __launch_bounds__(128)
void sa_q(const float* __restrict__ nsg, const float* __restrict__ nsb,
          const float* __restrict__ bq) {
    __shared__ float xn[DD];
    __shared__ float rs1[4], rs2[4];
    int row = blockIdx.x;
    int tid = threadIdx.x;
    int lane = tid & 31, w = tid >> 5;
    float x = g_slots[row * DD + tid];
    float s1 = x, s2 = x * x;
    #pragma unroll
    for (int o = 16; o > 0; o >>= 1) {
        s1 += __shfl_xor_sync(0xffffffffu, s1, o);
        s2 += __shfl_xor_sync(0xffffffffu, s2, o);
    }
    if (lane == 0) { rs1[w] = s1; rs2[w] = s2; }
    __syncthreads();
    float sum = rs1[0] + rs1[1] + rs1[2] + rs1[3];
    float sq  = rs2[0] + rs2[1] + rs2[2] + rs2[3];
    float mu = sum * (1.f / DD);
    float var = sq * (1.f / DD) - mu * mu;
    float rstd = rsqrtf(var + LN_EPS);
    xn[tid] = (x - mu) * rstd * nsg[tid] + nsb[tid];
    __syncthreads();
    float acc = bq[tid];
    #pragma unroll 4
    for (int i = 0; i < DD; ++i) acc += xn[i] * g_wqt[i * DD + tid];
    g_q[row * DD + tid] = acc;
}

// ---------------- fused attention over one 64-token chunk ----------------
#define ATTN_SMEM ((128 * 65 + SS * DD + CHUNK * SS + 2 * SS * DD) * 4)
__global__ __launch_bounds__(256, 4)
void sa_attn() {
    extern __shared__ float sm[];
    float* Kst  = sm;
    float* qs   = Kst + 128 * 65;
    float* att  = qs + SS * DD;
    float* updp = att + CHUNK * SS;
    const int tid = threadIdx.x;
    const int b = blockIdx.y;
    const int n0 = blockIdx.x * CHUNK;
    {
        const float4* s4 = (const float4*)(g_q + b * SS * DD);
        float4* d4 = (float4*)qs;
        for (int i = tid; i < SS * DD / 4; i += 256) d4[i] = s4[i];
    }
    const float* Kp = g_K + ((size_t)b * NN + n0) * DD;
    for (int i4 = tid; i4 < CHUNK * 32; i4 += 256) {
        float4 kv = ((const float4*)Kp)[i4];
        int tok = i4 >> 5;
        int c = (i4 & 31) * 4;
        Kst[(c + 0) * 65 + tok] = kv.x;
        Kst[(c + 1) * 65 + tok] = kv.y;
        Kst[(c + 2) * 65 + tok] = kv.z;
        Kst[(c + 3) * 65 + tok] = kv.w;
    }
    __syncthreads();
    {
        const int t = tid & 63;
        const int s0 = (tid >> 6) * 2;
        float l0 = 0.f, l1 = 0.f;
        const float* q0p = qs + s0 * DD;
        const float* q1p = qs + (s0 + 1) * DD;
        #pragma unroll 4
        for (int k = 0; k < DD; k += 4) {
            float k0 = Kst[(k + 0) * 65 + t];
            float k1 = Kst[(k + 1) * 65 + t];
            float k2 = Kst[(k + 2) * 65 + t];
            float k3 = Kst[(k + 3) * 65 + t];
            float4 a0 = *(const float4*)(q0p + k);
            float4 a1 = *(const float4*)(q1p + k);
            l0 += k0 * a0.x + k1 * a0.y + k2 * a0.z + k3 * a0.w;
            l1 += k0 * a1.x + k1 * a1.y + k2 * a1.z + k3 * a1.w;
        }
        att[t * 8 + s0]     = l0 * QK_SCALE;
        att[t * 8 + s0 + 1] = l1 * QK_SCALE;
    }
    __syncthreads();
    if (tid < CHUNK) {
        float l[8];
        #pragma unroll
        for (int s = 0; s < 8; ++s) l[s] = att[tid * 8 + s];
        float mx = l[0];
        #pragma unroll
        for (int s = 1; s < 8; ++s) mx = fmaxf(mx, l[s]);
        float sum = 0.f;
        #pragma unroll
        for (int s = 0; s < 8; ++s) { l[s] = expf(l[s] - mx); sum += l[s]; }
        float inv = 1.f / sum;
        #pragma unroll
        for (int s = 0; s < 8; ++s) att[tid * 8 + s] = l[s] * inv;
    }
    __syncthreads();
    {
        int w = tid >> 5, lane = tid & 31;
        float v = att[lane * 8 + w] + att[(lane + 32) * 8 + w];
        #pragma unroll
        for (int o = 16; o > 0; o >>= 1) v += __shfl_xor_sync(0xffffffffu, v, o);
        if (lane == 0) g_normp[((size_t)blockIdx.x * BB + b) * SS + w] = v;
    }
    const float* Vp = g_V + ((size_t)b * NN + n0) * DD;
    {
        const int g = tid >> 7;
        const int u = tid & 127;
        const int dp = (u & 63) * 2;
        const int shalf = u >> 6;
        float ax[4], ay[4];
        #pragma unroll
        for (int s = 0; s < 4; ++s) { ax[s] = 0.f; ay[s] = 0.f; }
        #pragma unroll 2
        for (int tt = 0; tt < 32; ++tt) {
            int t = g * 32 + tt;
            float2 vv = *(const float2*)(Vp + t * DD + dp);
            float4 w4 = *(const float4*)(att + t * 8 + shalf * 4);
            ax[0] += w4.x * vv.x; ay[0] += w4.x * vv.y;
            ax[1] += w4.y * vv.x; ay[1] += w4.y * vv.y;
            ax[2] += w4.z * vv.x; ay[2] += w4.z * vv.y;
            ax[3] += w4.w * vv.x; ay[3] += w4.w * vv.y;
        }
        #pragma unroll
        for (int s = 0; s < 4; ++s)
            *(float2*)(updp + (g * SS + shalf * 4 + s) * DD + dp)
                = make_float2(ax[s], ay[s]);
    }
    __syncthreads();
    float* dst = g_updp + ((size_t)blockIdx.x * BB + b) * (SS * DD);
    for (int o = tid; o < SS * DD; o += 256)
        dst[o] = updp[o] + updp[o + SS * DD];
}

// -------- fused chunk-reduce + GRU + MLP: ONE block per (b, slot), 512 blocks --
__global__ __launch_bounds__(128)
void sa_update(const float* __restrict__ bih, const float* __restrict__ bhh,
               const float* __restrict__ mg, const float* __restrict__ mb,
               const float* __restrict__ b1, const float* __restrict__ b2,
               float* __restrict__ outbuf, int write_out) {
    __shared__ float su[DD], sh[DD], sn[DD], xn[DD];
    __shared__ float h1s[HH];
    __shared__ float red[8];
    const int b = blockIdx.x >> 3;
    const int s = blockIdx.x & 7;
    const int j = threadIdx.x;
    const int lane = j & 31, w = j >> 5;
    // norm: warp 0 reduces 64 chunk partials for this slot
    if (w == 0) {
        float ns = g_normp[((size_t)lane * BB + b) * SS + s]
                 + g_normp[((size_t)(lane + 32) * BB + b) * SS + s];
        #pragma unroll
        for (int o = 16; o > 0; o >>= 1) ns += __shfl_xor_sync(0xffffffffu, ns, o);
        if (lane == 0) red[0] = fmaxf(ns, 1e-8f);
    }
    // update reduce: thread j sums its column over 64 chunks (coalesced rows)
    {
        float a0 = 0.f;
        const size_t o0 = (size_t)s * DD + j;
        #pragma unroll 8
        for (int c = 0; c < NCHUNK; ++c)
            a0 += g_updp[((size_t)c * BB + b) * (SS * DD) + o0];
        sh[j] = g_slots[(b * SS + s) * DD + j];
        __syncthreads();
        su[j] = a0 / red[0];
    }
    __syncthreads();
    float ir = 0, iz = 0, inn = 0, hr = 0, hz = 0, hn = 0;
    #pragma unroll 4
    for (int d = 0; d < DD; ++d) {
        float u = su[d], h = sh[d];
        ir  += g_wiht[d * 384 + j] * u;
        iz  += g_wiht[d * 384 + 128 + j] * u;
        inn += g_wiht[d * 384 + 256 + j] * u;
        hr  += g_whht[d * 384 + j] * h;
        hz  += g_whht[d * 384 + 128 + j] * h;
        hn  += g_whht[d * 384 + 256 + j] * h;
    }
    {
        float r = 1.f / (1.f + expf(-(ir + bih[j] + hr + bhh[j])));
        float z = 1.f / (1.f + expf(-(iz + bih[j + 128] + hz + bhh[j + 128])));
        float n = tanhf(inn + bih[j + 256] + r * (hn + bhh[j + 256]));
        sn[j] = (1.f - z) * n + z * sh[j];
    }
    __syncthreads();
    {   // LN over the 128 values of sn
        float a = sn[j];
        float s1 = a, s2 = a * a;
        #pragma unroll
        for (int o = 16; o > 0; o >>= 1) {
            s1 += __shfl_xor_sync(0xffffffffu, s1, o);
            s2 += __shfl_xor_sync(0xffffffffu, s2, o);
        }
        if (lane == 0) { red[w] = s1; red[w + 4] = s2; }
        __syncthreads();
        float m = (red[0] + red[1] + red[2] + red[3]) * (1.f / DD);
        float v = (red[4] + red[5] + red[6] + red[7]) * (1.f / DD) - m * m;
        float rs = rsqrtf(v + LN_EPS);
        xn[j] = (a - m) * rs * mg[j] + mb[j];
    }
    __syncthreads();
    {   // h1: thread owns cols j and j+128
        float a0 = 0, a1 = 0;
        #pragma unroll 4
        for (int d = 0; d < DD; ++d) {
            float x = xn[d];
            a0 += x * g_w1t[d * HH + j];
            a1 += x * g_w1t[d * HH + j + 128];
        }
        float g0 = a0 + b1[j], g1 = a1 + b1[j + 128];
        h1s[j]       = 0.5f * g0 * (1.f + erff(g0 * 0.7071067811865475f));
        h1s[j + 128] = 0.5f * g1 * (1.f + erff(g1 * 0.7071067811865475f));
    }
    __syncthreads();
    {
        float o = 0;
        #pragma unroll 4
        for (int m = 0; m < HH; ++m) o += h1s[m] * g_w2t[m * DD + j];
        float val = sn[j] + o + b2[j];
        if (write_out) outbuf[(b * SS + s) * DD + j] = val;
        else           g_slots[(b * SS + s) * DD + j] = val;
    }
}

// ---------------- launch ----------------
extern "C" void kernel_launch(void* const* d_in, const int* in_sizes, int n_in,
                              void* d_out, int out_size) {
    const float* inputs = (const float*)d_in[0];
    const float* noise  = (const float*)d_in[1];
    const float* mu     = (const float*)d_in[2];
    const float* lsig   = (const float*)d_in[3];
    const float* wq     = (const float*)d_in[4];
    const float* bq     = (const float*)d_in[5];
    const float* wk     = (const float*)d_in[6];
    const float* bk     = (const float*)d_in[7];
    const float* wv     = (const float*)d_in[8];
    const float* bv     = (const float*)d_in[9];
    const float* gwih   = (const float*)d_in[10];
    const float* gwhh   = (const float*)d_in[11];
    const float* gbih   = (const float*)d_in[12];
    const float* gbhh   = (const float*)d_in[13];
    const float* nsg    = (const float*)d_in[14];
    const float* nsb    = (const float*)d_in[15];
    const float* nig    = (const float*)d_in[16];
    const float* nib    = (const float*)d_in[17];
    const float* mlg    = (const float*)d_in[18];
    const float* mlb    = (const float*)d_in[19];
    const float* w1     = (const float*)d_in[20];
    const float* b1     = (const float*)d_in[21];
    const float* w2     = (const float*)d_in[22];
    const float* b2     = (const float*)d_in[23];
    float* out = (float*)d_out;

    cudaFuncSetAttribute(sa_kv,   cudaFuncAttributeMaxDynamicSharedMemorySize, KV_SMEM_TOTAL);
    cudaFuncSetAttribute(sa_attn, cudaFuncAttributeMaxDynamicSharedMemorySize, ATTN_SMEM);

    sa_prep<<<(DD * 384 + 255) / 256, 256>>>(wq, gwih, gwhh, w1, w2, mu, lsig, noise);
    sa_nop<<<1, 32>>>();
    sa_nop<<<1, 32>>>();
    sa_kv<<<148, 256, KV_SMEM_TOTAL>>>(inputs, nig, nib, bk, bv, wk, wv);
    for (int it = 0; it < N_ITERS; ++it) {
        sa_q<<<BB * SS, 128>>>(nsg, nsb, bq);
        dim3 agrid(NCHUNK, BB);
        sa_attn<<<agrid, 256, ATTN_SMEM>>>();
        sa_update<<<BB * SS, 128>>>(gbih, gbhh, mlg, mlb, b1, b2,
                                    out, it == N_ITERS - 1 ? 1 : 0);
    }
}

// round 14
// speedup vs baseline: 1.4527x; 1.0007x over previous
#include <cuda_runtime.h>
#include <cuda_bf16.h>
#include <math.h>
#include <stdint.h>

#define BB 64
#define NN 4096
#define DD 128
#define SS 8
#define HH 256
#define N_ITERS 3
#define LN_EPS 1e-5f
#define QK_SCALE 0.08838834764831845f
#define CHUNK 64
#define NCHUNK (NN / CHUNK)
#define PF 132   // K chunk smem pitch in floats

// ---------------- device scratch ----------------
__device__ float g_K[BB * NN * DD];
__device__ float g_V[BB * NN * DD];
__device__ float g_slots[BB * SS * DD];
__device__ float g_q[BB * SS * DD];
__device__ float g_updp[NCHUNK * BB * SS * DD];
__device__ float g_normp[NCHUNK * BB * SS];
__device__ float g_wqt[DD * DD];
__device__ float g_wiht[DD * 3 * DD];
__device__ float g_whht[DD * 3 * DD];
__device__ float g_w1t[DD * HH];
__device__ float g_w2t[HH * DD];

__device__ __forceinline__ uint32_t smem_u32(const void* p) {
    uint32_t a;
    asm("{ .reg .u64 t; cvta.to.shared.u64 t, %1; cvt.u32.u64 %0, t; }"
        : "=r"(a) : "l"(p));
    return a;
}
__device__ __forceinline__ void ldsm_x4(uint32_t* r, uint32_t addr) {
    asm volatile("ldmatrix.sync.aligned.m8n8.x4.shared.b16 {%0,%1,%2,%3}, [%4];"
                 : "=r"(r[0]), "=r"(r[1]), "=r"(r[2]), "=r"(r[3]) : "r"(addr));
}
__device__ __forceinline__ void ldsm_x2(uint32_t* r, uint32_t addr) {
    asm volatile("ldmatrix.sync.aligned.m8n8.x2.shared.b16 {%0,%1}, [%2];"
                 : "=r"(r[0]), "=r"(r[1]) : "r"(addr));
}
__device__ __forceinline__ void mma_bf16(float* c, const uint32_t* a, const uint32_t* b) {
    asm volatile(
        "mma.sync.aligned.m16n8k16.row.col.f32.bf16.bf16.f32 "
        "{%0,%1,%2,%3}, {%4,%5,%6,%7}, {%8,%9}, {%0,%1,%2,%3};"
        : "+f"(c[0]), "+f"(c[1]), "+f"(c[2]), "+f"(c[3])
        : "r"(a[0]), "r"(a[1]), "r"(a[2]), "r"(a[3]), "r"(b[0]), "r"(b[1]));
}

// smem layout for sa_kv (bytes); pitch 136 bf16 (272B) de-conflicts ldmatrix
#define PA 136
#define S_BIAS 0
#define S_BH 1024
#define S_BL (S_BH + 256 * PA * 2)
#define S_AH (S_BL + 256 * PA * 2)
#define S_AL (S_AH + 128 * PA * 2)
#define KV_SMEM_TOTAL (S_AL + 128 * PA * 2)

// ---------------- weight transposes + slot init ----------------
__global__ void sa_prep(const float* __restrict__ wq, const float* __restrict__ wih,
                        const float* __restrict__ whh, const float* __restrict__ w1,
                        const float* __restrict__ w2, const float* __restrict__ mu,
                        const float* __restrict__ ls, const float* __restrict__ noise) {
    int i = blockIdx.x * blockDim.x + threadIdx.x;
    if (i < DD * DD)  { int a = i / DD, j = i % DD; g_wqt[i] = wq[j * DD + a]; }
    if (i < DD * 384) { int d = i / 384, g = i % 384;
        g_wiht[i] = wih[g * DD + d]; g_whht[i] = whh[g * DD + d]; }
    if (i < DD * HH)  { int j = i / HH, m = i % HH; g_w1t[i] = w1[m * DD + j]; }
    if (i < HH * DD)  { int m = i / DD, j = i % DD; g_w2t[i] = w2[j * HH + m]; }
    if (i < SS * DD) {
        float v = mu[i] + expf(ls[i]) * noise[i];
        for (int b = 0; b < BB; ++b) g_slots[b * SS * DD + i] = v;
    }
}

// -------- LN(inputs) + K/V projection via mma.sync bf16-split (3 passes) -------
// (identical to round-13: 256 threads, 8 warps, warp = 16 rows x 256 cols)
__global__ __launch_bounds__(256, 1)
void sa_kv(const float* __restrict__ inp, const float* __restrict__ nig,
           const float* __restrict__ nib, const float* __restrict__ bk,
           const float* __restrict__ bv, const float* __restrict__ wk,
           const float* __restrict__ wv) {
    extern __shared__ __align__(128) char smem[];
    const uint32_t sb = smem_u32(smem);
    const int tid = threadIdx.x;
    const int wid = tid >> 5;
    const int lane = tid & 31;

    for (int idx = tid; idx < 256 * DD; idx += 256) {
        int row = idx >> 7, k = idx & 127;
        float w = (row < 128) ? wk[row * DD + k] : wv[(row - 128) * DD + k];
        __nv_bfloat16 hi = __float2bfloat16(w);
        __nv_bfloat16 lo = __float2bfloat16(w - __bfloat162float(hi));
        uint32_t off = (uint32_t)(row * PA + k) * 2;
        *(__nv_bfloat16*)(smem + S_BH + off) = hi;
        *(__nv_bfloat16*)(smem + S_BL + off) = lo;
    }
    for (int c = tid; c < 256; c += 256)
        *(float*)(smem + S_BIAS + c * 4) = (c < DD) ? bk[c] : bv[c - DD];

    float4 lg4 = *(const float4*)(nig + lane * 4);
    float4 lb4 = *(const float4*)(nib + lane * 4);

    const int a_rr = lane & 7;
    const int a_g  = lane >> 3;
    const int a_ro = a_rr + ((a_g & 1) ? 8 : 0);
    const int a_ko = (a_g & 2) ? 8 : 0;
    const int b_rr = lane & 7;
    const int b_ko = (lane & 8) ? 8 : 0;
    const int r0 = wid * 16;

    const int ntiles = BB * NN / 128;   // 2048
    for (int tile = blockIdx.x; tile < ntiles; tile += gridDim.x) {
        size_t m0 = (size_t)tile * 128;
        #pragma unroll
        for (int rr = 0; rr < 16; ++rr) {
            int row = wid * 16 + rr;
            float4 xv = *(const float4*)(inp + (m0 + row) * DD + lane * 4);
            float s1 = xv.x + xv.y + xv.z + xv.w;
            float s2 = xv.x * xv.x + xv.y * xv.y + xv.z * xv.z + xv.w * xv.w;
            #pragma unroll
            for (int o = 16; o > 0; o >>= 1) {
                s1 += __shfl_xor_sync(0xffffffffu, s1, o);
                s2 += __shfl_xor_sync(0xffffffffu, s2, o);
            }
            float muv = s1 * (1.f / DD);
            float var = s2 * (1.f / DD) - muv * muv;
            float rs = rsqrtf(var + LN_EPS);
            float x0 = (xv.x - muv) * rs * lg4.x + lb4.x;
            float x1 = (xv.y - muv) * rs * lg4.y + lb4.y;
            float x2 = (xv.z - muv) * rs * lg4.z + lb4.z;
            float x3 = (xv.w - muv) * rs * lg4.w + lb4.w;
            __nv_bfloat16 h0 = __float2bfloat16(x0), h1 = __float2bfloat16(x1);
            __nv_bfloat16 h2 = __float2bfloat16(x2), h3 = __float2bfloat16(x3);
            __nv_bfloat16 l0 = __float2bfloat16(x0 - __bfloat162float(h0));
            __nv_bfloat16 l1 = __float2bfloat16(x1 - __bfloat162float(h1));
            __nv_bfloat16 l2 = __float2bfloat16(x2 - __bfloat162float(h2));
            __nv_bfloat16 l3 = __float2bfloat16(x3 - __bfloat162float(h3));
            uint2 hv, lv;
            hv.x = ((uint32_t)__bfloat16_as_ushort(h1) << 16) | __bfloat16_as_ushort(h0);
            hv.y = ((uint32_t)__bfloat16_as_ushort(h3) << 16) | __bfloat16_as_ushort(h2);
            lv.x = ((uint32_t)__bfloat16_as_ushort(l1) << 16) | __bfloat16_as_ushort(l0);
            lv.y = ((uint32_t)__bfloat16_as_ushort(l3) << 16) | __bfloat16_as_ushort(l2);
            uint32_t off = (uint32_t)(row * PA + lane * 4) * 2;
            *(uint2*)(smem + S_AH + off) = hv;
            *(uint2*)(smem + S_AL + off) = lv;
        }
        __syncthreads();
        float acc[32][4];
        #pragma unroll
        for (int nt = 0; nt < 32; ++nt) {
            acc[nt][0] = 0.f; acc[nt][1] = 0.f; acc[nt][2] = 0.f; acc[nt][3] = 0.f;
        }
        #pragma unroll 1
        for (int ks = 0; ks < 8; ++ks) {
            int k0 = ks * 16;
            uint32_t ah[4], al[4];
            uint32_t aoff = (uint32_t)((r0 + a_ro) * PA + k0 + a_ko) * 2;
            ldsm_x4(ah, sb + S_AH + aoff);
            ldsm_x4(al, sb + S_AL + aoff);
            uint32_t boff = (uint32_t)(b_rr * PA + k0 + b_ko) * 2;
            #pragma unroll
            for (int nt = 0; nt < 32; ++nt) {
                uint32_t bo = boff + (uint32_t)(nt * 8 * PA) * 2;
                uint32_t bh[2], bl[2];
                ldsm_x2(bh, sb + S_BH + bo);
                ldsm_x2(bl, sb + S_BL + bo);
                mma_bf16(acc[nt], ah, bh);
                mma_bf16(acc[nt], ah, bl);
                mma_bf16(acc[nt], al, bh);
            }
        }
        __syncthreads();
        {
            int rbase = (int)(m0 + r0 + (lane >> 2));
            int cq = (lane & 3) * 2;
            #pragma unroll
            for (int nt = 0; nt < 32; ++nt) {
                int col = nt * 8 + cq;
                float2 bias = *(float2*)(smem + S_BIAS + col * 4);
                float* base = (nt < 16) ? g_K : g_V;
                int c = (nt < 16) ? col : col - 128;
                *(float2*)(base + (size_t)rbase * DD + c)
                    = make_float2(acc[nt][0] + bias.x, acc[nt][1] + bias.y);
                *(float2*)(base + (size_t)(rbase + 8) * DD + c)
                    = make_float2(acc[nt][2] + bias.x, acc[nt][3] + bias.y);
            }
        }
    }
}

// ---------------- q = LN(slots; ns) @ wq^T + bq ----------------
__global__ __launch_bounds__(128)
void sa_q(const float* __restrict__ nsg, const float* __restrict__ nsb,
          const float* __restrict__ bq) {
    __shared__ float xn[DD];
    __shared__ float rs1[4], rs2[4];
    int row = blockIdx.x;
    int tid = threadIdx.x;
    int lane = tid & 31, w = tid >> 5;
    float x = g_slots[row * DD + tid];
    float s1 = x, s2 = x * x;
    #pragma unroll
    for (int o = 16; o > 0; o >>= 1) {
        s1 += __shfl_xor_sync(0xffffffffu, s1, o);
        s2 += __shfl_xor_sync(0xffffffffu, s2, o);
    }
    if (lane == 0) { rs1[w] = s1; rs2[w] = s2; }
    __syncthreads();
    float sum = rs1[0] + rs1[1] + rs1[2] + rs1[3];
    float sq  = rs2[0] + rs2[1] + rs2[2] + rs2[3];
    float mu = sum * (1.f / DD);
    float var = sq * (1.f / DD) - mu * mu;
    float rstd = rsqrtf(var + LN_EPS);
    xn[tid] = (x - mu) * rstd * nsg[tid] + nsb[tid];
    __syncthreads();
    float acc = bq[tid];
    #pragma unroll 4
    for (int i = 0; i < DD; ++i) acc += xn[i] * g_wqt[i * DD + tid];
    g_q[row * DD + tid] = acc;
}

// ---------------- fused attention over one 64-token chunk ----------------
// K chunk stored UNtransposed [t][PF=132]: float4 fill + LDS.128 logits reads.
#define ATTN_SMEM ((CHUNK * PF + SS * DD + CHUNK * SS + 2 * SS * DD) * 4)
__global__ __launch_bounds__(256, 4)
void sa_attn() {
    extern __shared__ float sm[];
    float* Kst  = sm;                       // [t][PF]
    float* qs   = Kst + CHUNK * PF;         // [s][DD]
    float* att  = qs + SS * DD;             // [t][SS]
    float* updp = att + CHUNK * SS;         // [g][s][d]
    const int tid = threadIdx.x;
    const int b = blockIdx.y;
    const int n0 = blockIdx.x * CHUNK;
    {
        const float4* s4 = (const float4*)(g_q + b * SS * DD);
        float4* d4 = (float4*)qs;
        for (int i = tid; i < SS * DD / 4; i += 256) d4[i] = s4[i];
    }
    const float4* Kp4 = (const float4*)(g_K + ((size_t)b * NN + n0) * DD);
    for (int i4 = tid; i4 < CHUNK * 32; i4 += 256) {
        float4 kv = Kp4[i4];
        int tok = i4 >> 5;
        int c = i4 & 31;
        *(float4*)(Kst + tok * PF + c * 4) = kv;   // conflict-free
    }
    __syncthreads();
    {   // logits: t = tid&63, slot pair s0 = (tid>>6)*2; K row via LDS.128
        const int t = tid & 63;
        const int s0 = (tid >> 6) * 2;
        float l0 = 0.f, l1 = 0.f;
        const float* kp = Kst + t * PF;
        const float* q0p = qs + s0 * DD;
        const float* q1p = qs + (s0 + 1) * DD;
        #pragma unroll 8
        for (int k = 0; k < DD; k += 4) {
            float4 kk = *(const float4*)(kp + k);
            float4 a0 = *(const float4*)(q0p + k);
            float4 a1 = *(const float4*)(q1p + k);
            l0 += kk.x * a0.x + kk.y * a0.y + kk.z * a0.z + kk.w * a0.w;
            l1 += kk.x * a1.x + kk.y * a1.y + kk.z * a1.z + kk.w * a1.w;
        }
        att[t * 8 + s0]     = l0 * QK_SCALE;
        att[t * 8 + s0 + 1] = l1 * QK_SCALE;
    }
    __syncthreads();
    if (tid < CHUNK) {
        float l[8];
        #pragma unroll
        for (int s = 0; s < 8; ++s) l[s] = att[tid * 8 + s];
        float mx = l[0];
        #pragma unroll
        for (int s = 1; s < 8; ++s) mx = fmaxf(mx, l[s]);
        float sum = 0.f;
        #pragma unroll
        for (int s = 0; s < 8; ++s) { l[s] = expf(l[s] - mx); sum += l[s]; }
        float inv = 1.f / sum;
        #pragma unroll
        for (int s = 0; s < 8; ++s) att[tid * 8 + s] = l[s] * inv;
    }
    __syncthreads();
    {
        int w = tid >> 5, lane = tid & 31;
        float v = att[lane * 8 + w] + att[(lane + 32) * 8 + w];
        #pragma unroll
        for (int o = 16; o > 0; o >>= 1) v += __shfl_xor_sync(0xffffffffu, v, o);
        if (lane == 0) g_normp[((size_t)blockIdx.x * BB + b) * SS + w] = v;
    }
    const float* Vp = g_V + ((size_t)b * NN + n0) * DD;
    {
        const int g = tid >> 7;
        const int u = tid & 127;
        const int dp = (u & 63) * 2;
        const int shalf = u >> 6;
        float ax[4], ay[4];
        #pragma unroll
        for (int s = 0; s < 4; ++s) { ax[s] = 0.f; ay[s] = 0.f; }
        #pragma unroll 2
        for (int tt = 0; tt < 32; ++tt) {
            int t = g * 32 + tt;
            float2 vv = *(const float2*)(Vp + t * DD + dp);
            float4 w4 = *(const float4*)(att + t * 8 + shalf * 4);
            ax[0] += w4.x * vv.x; ay[0] += w4.x * vv.y;
            ax[1] += w4.y * vv.x; ay[1] += w4.y * vv.y;
            ax[2] += w4.z * vv.x; ay[2] += w4.z * vv.y;
            ax[3] += w4.w * vv.x; ay[3] += w4.w * vv.y;
        }
        #pragma unroll
        for (int s = 0; s < 4; ++s)
            *(float2*)(updp + (g * SS + shalf * 4 + s) * DD + dp)
                = make_float2(ax[s], ay[s]);
    }
    __syncthreads();
    float* dst = g_updp + ((size_t)blockIdx.x * BB + b) * (SS * DD);
    for (int o = tid; o < SS * DD; o += 256)
        dst[o] = updp[o] + updp[o + SS * DD];
}

// -------- fused chunk-reduce + GRU + MLP: ONE block per (b, slot), 512 blocks --
__global__ __launch_bounds__(128)
void sa_update(const float* __restrict__ bih, const float* __restrict__ bhh,
               const float* __restrict__ mg, const float* __restrict__ mb,
               const float* __restrict__ b1, const float* __restrict__ b2,
               float* __restrict__ outbuf, int write_out) {
    __shared__ float su[DD], sh[DD], sn[DD], xn[DD];
    __shared__ float h1s[HH];
    __shared__ float red[8];
    const int b = blockIdx.x >> 3;
    const int s = blockIdx.x & 7;
    const int j = threadIdx.x;
    const int lane = j & 31, w = j >> 5;
    if (w == 0) {
        float ns = g_normp[((size_t)lane * BB + b) * SS + s]
                 + g_normp[((size_t)(lane + 32) * BB + b) * SS + s];
        #pragma unroll
        for (int o = 16; o > 0; o >>= 1) ns += __shfl_xor_sync(0xffffffffu, ns, o);
        if (lane == 0) red[0] = fmaxf(ns, 1e-8f);
    }
    {
        float a0 = 0.f;
        const size_t o0 = (size_t)s * DD + j;
        #pragma unroll 8
        for (int c = 0; c < NCHUNK; ++c)
            a0 += g_updp[((size_t)c * BB + b) * (SS * DD) + o0];
        sh[j] = g_slots[(b * SS + s) * DD + j];
        __syncthreads();
        su[j] = a0 / red[0];
    }
    __syncthreads();
    float ir = 0, iz = 0, inn = 0, hr = 0, hz = 0, hn = 0;
    #pragma unroll 4
    for (int d = 0; d < DD; ++d) {
        float u = su[d], h = sh[d];
        ir  += g_wiht[d * 384 + j] * u;
        iz  += g_wiht[d * 384 + 128 + j] * u;
        inn += g_wiht[d * 384 + 256 + j] * u;
        hr  += g_whht[d * 384 + j] * h;
        hz  += g_whht[d * 384 + 128 + j] * h;
        hn  += g_whht[d * 384 + 256 + j] * h;
    }
    {
        float r = 1.f / (1.f + expf(-(ir + bih[j] + hr + bhh[j])));
        float z = 1.f / (1.f + expf(-(iz + bih[j + 128] + hz + bhh[j + 128])));
        float n = tanhf(inn + bih[j + 256] + r * (hn + bhh[j + 256]));
        sn[j] = (1.f - z) * n + z * sh[j];
    }
    __syncthreads();
    {
        float a = sn[j];
        float s1 = a, s2 = a * a;
        #pragma unroll
        for (int o = 16; o > 0; o >>= 1) {
            s1 += __shfl_xor_sync(0xffffffffu, s1, o);
            s2 += __shfl_xor_sync(0xffffffffu, s2, o);
        }
        if (lane == 0) { red[w] = s1; red[w + 4] = s2; }
        __syncthreads();
        float m = (red[0] + red[1] + red[2] + red[3]) * (1.f / DD);
        float v = (red[4] + red[5] + red[6] + red[7]) * (1.f / DD) - m * m;
        float rs = rsqrtf(v + LN_EPS);
        xn[j] = (a - m) * rs * mg[j] + mb[j];
    }
    __syncthreads();
    {
        float a0 = 0, a1 = 0;
        #pragma unroll 4
        for (int d = 0; d < DD; ++d) {
            float x = xn[d];
            a0 += x * g_w1t[d * HH + j];
            a1 += x * g_w1t[d * HH + j + 128];
        }
        float g0 = a0 + b1[j], g1 = a1 + b1[j + 128];
        h1s[j]       = 0.5f * g0 * (1.f + erff(g0 * 0.7071067811865475f));
        h1s[j + 128] = 0.5f * g1 * (1.f + erff(g1 * 0.7071067811865475f));
    }
    __syncthreads();
    {
        float o = 0;
        #pragma unroll 4
        for (int m = 0; m < HH; ++m) o += h1s[m] * g_w2t[m * DD + j];
        float val = sn[j] + o + b2[j];
        if (write_out) outbuf[(b * SS + s) * DD + j] = val;
        else           g_slots[(b * SS + s) * DD + j] = val;
    }
}

// ---------------- launch ----------------
extern "C" void kernel_launch(void* const* d_in, const int* in_sizes, int n_in,
                              void* d_out, int out_size) {
    const float* inputs = (const float*)d_in[0];
    const float* noise  = (const float*)d_in[1];
    const float* mu     = (const float*)d_in[2];
    const float* lsig   = (const float*)d_in[3];
    const float* wq     = (const float*)d_in[4];
    const float* bq     = (const float*)d_in[5];
    const float* wk     = (const float*)d_in[6];
    const float* bk     = (const float*)d_in[7];
    const float* wv     = (const float*)d_in[8];
    const float* bv     = (const float*)d_in[9];
    const float* gwih   = (const float*)d_in[10];
    const float* gwhh   = (const float*)d_in[11];
    const float* gbih   = (const float*)d_in[12];
    const float* gbhh   = (const float*)d_in[13];
    const float* nsg    = (const float*)d_in[14];
    const float* nsb    = (const float*)d_in[15];
    const float* nig    = (const float*)d_in[16];
    const float* nib    = (const float*)d_in[17];
    const float* mlg    = (const float*)d_in[18];
    const float* mlb    = (const float*)d_in[19];
    const float* w1     = (const float*)d_in[20];
    const float* b1     = (const float*)d_in[21];
    const float* w2     = (const float*)d_in[22];
    const float* b2     = (const float*)d_in[23];
    float* out = (float*)d_out;

    cudaFuncSetAttribute(sa_kv,   cudaFuncAttributeMaxDynamicSharedMemorySize, KV_SMEM_TOTAL);
    cudaFuncSetAttribute(sa_attn, cudaFuncAttributeMaxDynamicSharedMemorySize, ATTN_SMEM);

    sa_prep<<<(DD * 384 + 255) / 256, 256>>>(wq, gwih, gwhh, w1, w2, mu, lsig, noise);
    sa_kv<<<148, 256, KV_SMEM_TOTAL>>>(inputs, nig, nib, bk, bv, wk, wv);
    for (int it = 0; it < N_ITERS; ++it) {
        sa_q<<<BB * SS, 128>>>(nsg, nsb, bq);
        dim3 agrid(NCHUNK, BB);
        sa_attn<<<agrid, 256, ATTN_SMEM>>>();
        sa_update<<<BB * SS, 128>>>(gbih, gbhh, mlg, mlb, b1, b2,
                                    out, it == N_ITERS - 1 ? 1 : 0);
    }
}

// round 15
// speedup vs baseline: 1.6094x; 1.1079x over previous
#include <cuda_runtime.h>
#include <cuda_bf16.h>
#include <math.h>
#include <stdint.h>

#define BB 64
#define NN 4096
#define DD 128
#define SS 8
#define HH 256
#define N_ITERS 3
#define LN_EPS 1e-5f
#define QK_SCALE 0.08838834764831845f
#define CHUNK 64
#define NCHUNK (NN / CHUNK)
#define PF 132   // K chunk smem pitch in floats

// ---------------- device scratch ----------------
__device__ float g_K[BB * NN * DD];
__device__ float g_V[BB * NN * DD];
__device__ float g_slots[BB * SS * DD];
__device__ float g_q[BB * SS * DD];
__device__ float g_updp[NCHUNK * BB * SS * DD];
__device__ float g_normp[NCHUNK * BB * SS];
__device__ float g_wqt[DD * DD];
__device__ float g_wiht[DD * 3 * DD];
__device__ float g_whht[DD * 3 * DD];
__device__ float g_w1t[DD * HH];
__device__ float g_w2t[HH * DD];

__device__ __forceinline__ uint32_t smem_u32(const void* p) {
    uint32_t a;
    asm("{ .reg .u64 t; cvta.to.shared.u64 t, %1; cvt.u32.u64 %0, t; }"
        : "=r"(a) : "l"(p));
    return a;
}
__device__ __forceinline__ void ldsm_x4(uint32_t* r, uint32_t addr) {
    asm volatile("ldmatrix.sync.aligned.m8n8.x4.shared.b16 {%0,%1,%2,%3}, [%4];"
                 : "=r"(r[0]), "=r"(r[1]), "=r"(r[2]), "=r"(r[3]) : "r"(addr));
}
__device__ __forceinline__ void ldsm_x2(uint32_t* r, uint32_t addr) {
    asm volatile("ldmatrix.sync.aligned.m8n8.x2.shared.b16 {%0,%1}, [%2];"
                 : "=r"(r[0]), "=r"(r[1]) : "r"(addr));
}
__device__ __forceinline__ void mma_bf16(float* c, const uint32_t* a, const uint32_t* b) {
    asm volatile(
        "mma.sync.aligned.m16n8k16.row.col.f32.bf16.bf16.f32 "
        "{%0,%1,%2,%3}, {%4,%5,%6,%7}, {%8,%9}, {%0,%1,%2,%3};"
        : "+f"(c[0]), "+f"(c[1]), "+f"(c[2]), "+f"(c[3])
        : "r"(a[0]), "r"(a[1]), "r"(a[2]), "r"(a[3]), "r"(b[0]), "r"(b[1]));
}

// smem layout for sa_kv (bytes); pitch 136 bf16 (272B) de-conflicts ldmatrix
#define PA 136
#define S_BIAS 0
#define S_BH 1024
#define S_BL (S_BH + 256 * PA * 2)
#define S_AH (S_BL + 256 * PA * 2)
#define S_AL (S_AH + 128 * PA * 2)
#define KV_SMEM_TOTAL (S_AL + 128 * PA * 2)

// ---------------- weight transposes + slot init ----------------
__global__ void sa_prep(const float* __restrict__ wq, const float* __restrict__ wih,
                        const float* __restrict__ whh, const float* __restrict__ w1,
                        const float* __restrict__ w2, const float* __restrict__ mu,
                        const float* __restrict__ ls, const float* __restrict__ noise) {
    int i = blockIdx.x * blockDim.x + threadIdx.x;
    if (i < DD * DD)  { int a = i / DD, j = i % DD; g_wqt[i] = wq[j * DD + a]; }
    if (i < DD * 384) { int d = i / 384, g = i % 384;
        g_wiht[i] = wih[g * DD + d]; g_whht[i] = whh[g * DD + d]; }
    if (i < DD * HH)  { int j = i / HH, m = i % HH; g_w1t[i] = w1[m * DD + j]; }
    if (i < HH * DD)  { int m = i / DD, j = i % DD; g_w2t[i] = w2[j * HH + m]; }
    if (i < SS * DD) {
        float v = mu[i] + expf(ls[i]) * noise[i];
        for (int b = 0; b < BB; ++b) g_slots[b * SS * DD + i] = v;
    }
}

// -------- LN(inputs) + K/V projection via mma.sync bf16-split (3 passes) -------
__global__ __launch_bounds__(256, 1)
void sa_kv(const float* __restrict__ inp, const float* __restrict__ nig,
           const float* __restrict__ nib, const float* __restrict__ bk,
           const float* __restrict__ bv, const float* __restrict__ wk,
           const float* __restrict__ wv) {
    extern __shared__ __align__(128) char smem[];
    const uint32_t sb = smem_u32(smem);
    const int tid = threadIdx.x;
    const int wid = tid >> 5;
    const int lane = tid & 31;

    for (int idx = tid; idx < 256 * DD; idx += 256) {
        int row = idx >> 7, k = idx & 127;
        float w = (row < 128) ? wk[row * DD + k] : wv[(row - 128) * DD + k];
        __nv_bfloat16 hi = __float2bfloat16(w);
        __nv_bfloat16 lo = __float2bfloat16(w - __bfloat162float(hi));
        uint32_t off = (uint32_t)(row * PA + k) * 2;
        *(__nv_bfloat16*)(smem + S_BH + off) = hi;
        *(__nv_bfloat16*)(smem + S_BL + off) = lo;
    }
    for (int c = tid; c < 256; c += 256)
        *(float*)(smem + S_BIAS + c * 4) = (c < DD) ? bk[c] : bv[c - DD];

    float4 lg4 = *(const float4*)(nig + lane * 4);
    float4 lb4 = *(const float4*)(nib + lane * 4);

    const int a_rr = lane & 7;
    const int a_g  = lane >> 3;
    const int a_ro = a_rr + ((a_g & 1) ? 8 : 0);
    const int a_ko = (a_g & 2) ? 8 : 0;
    const int b_rr = lane & 7;
    const int b_ko = (lane & 8) ? 8 : 0;
    const int r0 = wid * 16;

    const int ntiles = BB * NN / 128;   // 2048
    for (int tile = blockIdx.x; tile < ntiles; tile += gridDim.x) {
        size_t m0 = (size_t)tile * 128;
        #pragma unroll
        for (int rr = 0; rr < 16; ++rr) {
            int row = wid * 16 + rr;
            float4 xv = *(const float4*)(inp + (m0 + row) * DD + lane * 4);
            float s1 = xv.x + xv.y + xv.z + xv.w;
            float s2 = xv.x * xv.x + xv.y * xv.y + xv.z * xv.z + xv.w * xv.w;
            #pragma unroll
            for (int o = 16; o > 0; o >>= 1) {
                s1 += __shfl_xor_sync(0xffffffffu, s1, o);
                s2 += __shfl_xor_sync(0xffffffffu, s2, o);
            }
            float muv = s1 * (1.f / DD);
            float var = s2 * (1.f / DD) - muv * muv;
            float rs = rsqrtf(var + LN_EPS);
            float x0 = (xv.x - muv) * rs * lg4.x + lb4.x;
            float x1 = (xv.y - muv) * rs * lg4.y + lb4.y;
            float x2 = (xv.z - muv) * rs * lg4.z + lb4.z;
            float x3 = (xv.w - muv) * rs * lg4.w + lb4.w;
            __nv_bfloat16 h0 = __float2bfloat16(x0), h1 = __float2bfloat16(x1);
            __nv_bfloat16 h2 = __float2bfloat16(x2), h3 = __float2bfloat16(x3);
            __nv_bfloat16 l0 = __float2bfloat16(x0 - __bfloat162float(h0));
            __nv_bfloat16 l1 = __float2bfloat16(x1 - __bfloat162float(h1));
            __nv_bfloat16 l2 = __float2bfloat16(x2 - __bfloat162float(h2));
            __nv_bfloat16 l3 = __float2bfloat16(x3 - __bfloat162float(h3));
            uint2 hv, lv;
            hv.x = ((uint32_t)__bfloat16_as_ushort(h1) << 16) | __bfloat16_as_ushort(h0);
            hv.y = ((uint32_t)__bfloat16_as_ushort(h3) << 16) | __bfloat16_as_ushort(h2);
            lv.x = ((uint32_t)__bfloat16_as_ushort(l1) << 16) | __bfloat16_as_ushort(l0);
            lv.y = ((uint32_t)__bfloat16_as_ushort(l3) << 16) | __bfloat16_as_ushort(l2);
            uint32_t off = (uint32_t)(row * PA + lane * 4) * 2;
            *(uint2*)(smem + S_AH + off) = hv;
            *(uint2*)(smem + S_AL + off) = lv;
        }
        __syncthreads();
        float acc[32][4];
        #pragma unroll
        for (int nt = 0; nt < 32; ++nt) {
            acc[nt][0] = 0.f; acc[nt][1] = 0.f; acc[nt][2] = 0.f; acc[nt][3] = 0.f;
        }
        #pragma unroll 1
        for (int ks = 0; ks < 8; ++ks) {
            int k0 = ks * 16;
            uint32_t ah[4], al[4];
            uint32_t aoff = (uint32_t)((r0 + a_ro) * PA + k0 + a_ko) * 2;
            ldsm_x4(ah, sb + S_AH + aoff);
            ldsm_x4(al, sb + S_AL + aoff);
            uint32_t boff = (uint32_t)(b_rr * PA + k0 + b_ko) * 2;
            #pragma unroll
            for (int nt = 0; nt < 32; ++nt) {
                uint32_t bo = boff + (uint32_t)(nt * 8 * PA) * 2;
                uint32_t bh[2], bl[2];
                ldsm_x2(bh, sb + S_BH + bo);
                ldsm_x2(bl, sb + S_BL + bo);
                mma_bf16(acc[nt], ah, bh);
                mma_bf16(acc[nt], ah, bl);
                mma_bf16(acc[nt], al, bh);
            }
        }
        __syncthreads();
        {
            int rbase = (int)(m0 + r0 + (lane >> 2));
            int cq = (lane & 3) * 2;
            #pragma unroll
            for (int nt = 0; nt < 32; ++nt) {
                int col = nt * 8 + cq;
                float2 bias = *(float2*)(smem + S_BIAS + col * 4);
                float* base = (nt < 16) ? g_K : g_V;
                int c = (nt < 16) ? col : col - 128;
                *(float2*)(base + (size_t)rbase * DD + c)
                    = make_float2(acc[nt][0] + bias.x, acc[nt][1] + bias.y);
                *(float2*)(base + (size_t)(rbase + 8) * DD + c)
                    = make_float2(acc[nt][2] + bias.x, acc[nt][3] + bias.y);
            }
        }
    }
}

// ---------------- q = LN(slots; ns) @ wq^T + bq ----------------
__global__ __launch_bounds__(128)
void sa_q(const float* __restrict__ nsg, const float* __restrict__ nsb,
          const float* __restrict__ bq) {
    __shared__ float xn[DD];
    __shared__ float rs1[4], rs2[4];
    int row = blockIdx.x;
    int tid = threadIdx.x;
    int lane = tid & 31, w = tid >> 5;
    float x = g_slots[row * DD + tid];
    float s1 = x, s2 = x * x;
    #pragma unroll
    for (int o = 16; o > 0; o >>= 1) {
        s1 += __shfl_xor_sync(0xffffffffu, s1, o);
        s2 += __shfl_xor_sync(0xffffffffu, s2, o);
    }
    if (lane == 0) { rs1[w] = s1; rs2[w] = s2; }
    __syncthreads();
    float sum = rs1[0] + rs1[1] + rs1[2] + rs1[3];
    float sq  = rs2[0] + rs2[1] + rs2[2] + rs2[3];
    float mu = sum * (1.f / DD);
    float var = sq * (1.f / DD) - mu * mu;
    float rstd = rsqrtf(var + LN_EPS);
    xn[tid] = (x - mu) * rstd * nsg[tid] + nsb[tid];
    __syncthreads();
    float acc = bq[tid];
    #pragma unroll 4
    for (int i = 0; i < DD; ++i) acc += xn[i] * g_wqt[i * DD + tid];
    g_q[row * DD + tid] = acc;
}

// ---------------- fused attention over one 64-token chunk ----------------
// K chunk [t][PF=132] (LDS.128 logits); V pass: each element loaded ONCE,
// thread owns dp=(tid&63)*2 over all 8 slots, token group tq = tid>>6.
#define ATTN_SMEM ((CHUNK * PF + SS * DD + CHUNK * SS + 2 * SS * DD) * 4)
__global__ __launch_bounds__(256, 4)
void sa_attn() {
    extern __shared__ float sm[];
    float* Kst  = sm;                       // [t][PF]
    float* qs   = Kst + CHUNK * PF;         // [s][DD]
    float* att  = qs + SS * DD;             // [t][SS]
    float* updp = att + CHUNK * SS;         // [2][SS*DD]
    const int tid = threadIdx.x;
    const int b = blockIdx.y;
    const int n0 = blockIdx.x * CHUNK;
    {
        const float4* s4 = (const float4*)(g_q + b * SS * DD);
        float4* d4 = (float4*)qs;
        for (int i = tid; i < SS * DD / 4; i += 256) d4[i] = s4[i];
    }
    const float4* Kp4 = (const float4*)(g_K + ((size_t)b * NN + n0) * DD);
    for (int i4 = tid; i4 < CHUNK * 32; i4 += 256) {
        float4 kv = Kp4[i4];
        int tok = i4 >> 5;
        int c = i4 & 31;
        *(float4*)(Kst + tok * PF + c * 4) = kv;   // conflict-free
    }
    __syncthreads();
    {   // logits: t = tid&63, slot pair s0 = (tid>>6)*2; K row via LDS.128
        const int t = tid & 63;
        const int s0 = (tid >> 6) * 2;
        float l0 = 0.f, l1 = 0.f;
        const float* kp = Kst + t * PF;
        const float* q0p = qs + s0 * DD;
        const float* q1p = qs + (s0 + 1) * DD;
        #pragma unroll 8
        for (int k = 0; k < DD; k += 4) {
            float4 kk = *(const float4*)(kp + k);
            float4 a0 = *(const float4*)(q0p + k);
            float4 a1 = *(const float4*)(q1p + k);
            l0 += kk.x * a0.x + kk.y * a0.y + kk.z * a0.z + kk.w * a0.w;
            l1 += kk.x * a1.x + kk.y * a1.y + kk.z * a1.z + kk.w * a1.w;
        }
        att[t * 8 + s0]     = l0 * QK_SCALE;
        att[t * 8 + s0 + 1] = l1 * QK_SCALE;
    }
    __syncthreads();
    if (tid < CHUNK) {
        float l[8];
        #pragma unroll
        for (int s = 0; s < 8; ++s) l[s] = att[tid * 8 + s];
        float mx = l[0];
        #pragma unroll
        for (int s = 1; s < 8; ++s) mx = fmaxf(mx, l[s]);
        float sum = 0.f;
        #pragma unroll
        for (int s = 0; s < 8; ++s) { l[s] = expf(l[s] - mx); sum += l[s]; }
        float inv = 1.f / sum;
        #pragma unroll
        for (int s = 0; s < 8; ++s) att[tid * 8 + s] = l[s] * inv;
    }
    __syncthreads();
    {
        int w = tid >> 5, lane = tid & 31;
        float v = att[lane * 8 + w] + att[(lane + 32) * 8 + w];
        #pragma unroll
        for (int o = 16; o > 0; o >>= 1) v += __shfl_xor_sync(0xffffffffu, v, o);
        if (lane == 0) g_normp[((size_t)blockIdx.x * BB + b) * SS + w] = v;
    }
    const float* Vp = g_V + ((size_t)b * NN + n0) * DD;
    {   // AV: thread (tq, u): tokens tq*16..+15, d = 2u, 2u+1, all 8 slots
        const int tq = tid >> 6;
        const int u = tid & 63;
        const int dp = u * 2;
        float ax[8], ay[8];
        #pragma unroll
        for (int s = 0; s < 8; ++s) { ax[s] = 0.f; ay[s] = 0.f; }
        #pragma unroll 4
        for (int tt = 0; tt < 16; ++tt) {
            int t = tq * 16 + tt;
            float2 vv = *(const float2*)(Vp + t * DD + dp);
            float4 w0 = *(const float4*)(att + t * 8);
            float4 w1 = *(const float4*)(att + t * 8 + 4);
            ax[0] += w0.x * vv.x; ay[0] += w0.x * vv.y;
            ax[1] += w0.y * vv.x; ay[1] += w0.y * vv.y;
            ax[2] += w0.z * vv.x; ay[2] += w0.z * vv.y;
            ax[3] += w0.w * vv.x; ay[3] += w0.w * vv.y;
            ax[4] += w1.x * vv.x; ay[4] += w1.x * vv.y;
            ax[5] += w1.y * vv.x; ay[5] += w1.y * vv.y;
            ax[6] += w1.z * vv.x; ay[6] += w1.z * vv.y;
            ax[7] += w1.w * vv.x; ay[7] += w1.w * vv.y;
        }
        // tq0/tq1 write the two buffers; sync; tq2/tq3 add into them
        float* buf = updp + (tq & 1) * (SS * DD);
        if (tq < 2) {
            #pragma unroll
            for (int s = 0; s < 8; ++s)
                *(float2*)(buf + s * DD + dp) = make_float2(ax[s], ay[s]);
        }
        __syncthreads();
        if (tq >= 2) {
            #pragma unroll
            for (int s = 0; s < 8; ++s) {
                float2 old = *(float2*)(buf + s * DD + dp);
                *(float2*)(buf + s * DD + dp)
                    = make_float2(old.x + ax[s], old.y + ay[s]);
            }
        }
    }
    __syncthreads();
    float* dst = g_updp + ((size_t)blockIdx.x * BB + b) * (SS * DD);
    for (int o = tid; o < SS * DD; o += 256)
        dst[o] = updp[o] + updp[o + SS * DD];
}

// -------- fused chunk-reduce + GRU + MLP: ONE block per (b, slot), 512 blocks --
__global__ __launch_bounds__(128)
void sa_update(const float* __restrict__ bih, const float* __restrict__ bhh,
               const float* __restrict__ mg, const float* __restrict__ mb,
               const float* __restrict__ b1, const float* __restrict__ b2,
               float* __restrict__ outbuf, int write_out) {
    __shared__ float su[DD], sh[DD], sn[DD], xn[DD];
    __shared__ float h1s[HH];
    __shared__ float red[8];
    const int b = blockIdx.x >> 3;
    const int s = blockIdx.x & 7;
    const int j = threadIdx.x;
    const int lane = j & 31, w = j >> 5;
    if (w == 0) {
        float ns = g_normp[((size_t)lane * BB + b) * SS + s]
                 + g_normp[((size_t)(lane + 32) * BB + b) * SS + s];
        #pragma unroll
        for (int o = 16; o > 0; o >>= 1) ns += __shfl_xor_sync(0xffffffffu, ns, o);
        if (lane == 0) red[0] = fmaxf(ns, 1e-8f);
    }
    {
        float a0 = 0.f;
        const size_t o0 = (size_t)s * DD + j;
        #pragma unroll 8
        for (int c = 0; c < NCHUNK; ++c)
            a0 += g_updp[((size_t)c * BB + b) * (SS * DD) + o0];
        sh[j] = g_slots[(b * SS + s) * DD + j];
        __syncthreads();
        su[j] = a0 / red[0];
    }
    __syncthreads();
    float ir = 0, iz = 0, inn = 0, hr = 0, hz = 0, hn = 0;
    #pragma unroll 4
    for (int d = 0; d < DD; ++d) {
        float u = su[d], h = sh[d];
        ir  += g_wiht[d * 384 + j] * u;
        iz  += g_wiht[d * 384 + 128 + j] * u;
        inn += g_wiht[d * 384 + 256 + j] * u;
        hr  += g_whht[d * 384 + j] * h;
        hz  += g_whht[d * 384 + 128 + j] * h;
        hn  += g_whht[d * 384 + 256 + j] * h;
    }
    {
        float r = 1.f / (1.f + expf(-(ir + bih[j] + hr + bhh[j])));
        float z = 1.f / (1.f + expf(-(iz + bih[j + 128] + hz + bhh[j + 128])));
        float n = tanhf(inn + bih[j + 256] + r * (hn + bhh[j + 256]));
        sn[j] = (1.f - z) * n + z * sh[j];
    }
    __syncthreads();
    {
        float a = sn[j];
        float s1 = a, s2 = a * a;
        #pragma unroll
        for (int o = 16; o > 0; o >>= 1) {
            s1 += __shfl_xor_sync(0xffffffffu, s1, o);
            s2 += __shfl_xor_sync(0xffffffffu, s2, o);
        }
        if (lane == 0) { red[w] = s1; red[w + 4] = s2; }
        __syncthreads();
        float m = (red[0] + red[1] + red[2] + red[3]) * (1.f / DD);
        float v = (red[4] + red[5] + red[6] + red[7]) * (1.f / DD) - m * m;
        float rs = rsqrtf(v + LN_EPS);
        xn[j] = (a - m) * rs * mg[j] + mb[j];
    }
    __syncthreads();
    {
        float a0 = 0, a1 = 0;
        #pragma unroll 4
        for (int d = 0; d < DD; ++d) {
            float x = xn[d];
            a0 += x * g_w1t[d * HH + j];
            a1 += x * g_w1t[d * HH + j + 128];
        }
        float g0 = a0 + b1[j], g1 = a1 + b1[j + 128];
        h1s[j]       = 0.5f * g0 * (1.f + erff(g0 * 0.7071067811865475f));
        h1s[j + 128] = 0.5f * g1 * (1.f + erff(g1 * 0.7071067811865475f));
    }
    __syncthreads();
    {
        float o = 0;
        #pragma unroll 4
        for (int m = 0; m < HH; ++m) o += h1s[m] * g_w2t[m * DD + j];
        float val = sn[j] + o + b2[j];
        if (write_out) outbuf[(b * SS + s) * DD + j] = val;
        else           g_slots[(b * SS + s) * DD + j] = val;
    }
}

// ---------------- launch ----------------
extern "C" void kernel_launch(void* const* d_in, const int* in_sizes, int n_in,
                              void* d_out, int out_size) {
    const float* inputs = (const float*)d_in[0];
    const float* noise  = (const float*)d_in[1];
    const float* mu     = (const float*)d_in[2];
    const float* lsig   = (const float*)d_in[3];
    const float* wq     = (const float*)d_in[4];
    const float* bq     = (const float*)d_in[5];
    const float* wk     = (const float*)d_in[6];
    const float* bk     = (const float*)d_in[7];
    const float* wv     = (const float*)d_in[8];
    const float* bv     = (const float*)d_in[9];
    const float* gwih   = (const float*)d_in[10];
    const float* gwhh   = (const float*)d_in[11];
    const float* gbih   = (const float*)d_in[12];
    const float* gbhh   = (const float*)d_in[13];
    const float* nsg    = (const float*)d_in[14];
    const float* nsb    = (const float*)d_in[15];
    const float* nig    = (const float*)d_in[16];
    const float* nib    = (const float*)d_in[17];
    const float* mlg    = (const float*)d_in[18];
    const float* mlb    = (const float*)d_in[19];
    const float* w1     = (const float*)d_in[20];
    const float* b1     = (const float*)d_in[21];
    const float* w2     = (const float*)d_in[22];
    const float* b2     = (const float*)d_in[23];
    float* out = (float*)d_out;

    cudaFuncSetAttribute(sa_kv,   cudaFuncAttributeMaxDynamicSharedMemorySize, KV_SMEM_TOTAL);
    cudaFuncSetAttribute(sa_attn, cudaFuncAttributeMaxDynamicSharedMemorySize, ATTN_SMEM);

    sa_prep<<<(DD * 384 + 255) / 256, 256>>>(wq, gwih, gwhh, w1, w2, mu, lsig, noise);
    sa_kv<<<148, 256, KV_SMEM_TOTAL>>>(inputs, nig, nib, bk, bv, wk, wv);
    for (int it = 0; it < N_ITERS; ++it) {
        sa_q<<<BB * SS, 128>>>(nsg, nsb, bq);
        dim3 agrid(NCHUNK, BB);
        sa_attn<<<agrid, 256, ATTN_SMEM>>>();
        sa_update<<<BB * SS, 128>>>(gbih, gbhh, mlg, mlb, b1, b2,
                                    out, it == N_ITERS - 1 ? 1 : 0);
    }
}